// round 6
// baseline (speedup 1.0000x reference)
#include <cuda_runtime.h>

#define DIM   64
#define TILE  128
#define NT    256
#define NSTEP 2

typedef unsigned long long u64;

// ---- packed f32x2 helpers ----
__device__ __forceinline__ u64 fma2(u64 a, u64 b, u64 c){
    u64 d; asm("fma.rn.f32x2 %0, %1, %2, %3;" : "=l"(d) : "l"(a), "l"(b), "l"(c)); return d;
}
__device__ __forceinline__ u64 pack2(float lo, float hi){
    u64 r; asm("mov.b64 %0, {%1, %2};" : "=l"(r) : "f"(lo), "f"(hi)); return r;
}
__device__ __forceinline__ u64 dup2(float a){ return pack2(a, a); }
__device__ __forceinline__ float2 unpk(u64 v){
    float2 f; asm("mov.b64 {%0, %1}, %2;" : "=f"(f.x), "=f"(f.y) : "l"(v)); return f;
}

// smooth_leaky_relu: 0.1*x + 0.9*softplus(x), numerically stable
// (MUFU exp+log kept on the MUFU pipe — overlaps the fma-pipe GEMM at 4 warps/SMSP)
__device__ __forceinline__ float act(float x){
    float sp = fmaxf(x, 0.f) + __logf(1.f + __expf(-fabsf(x)));
    return fmaf(0.9f, sp, 0.1f * x);
}

// One CTA integrates a TILE x 64 slab through all NSTEP RK4 steps.
// NT=256: each thread owns 4 rows (stride-32 interleaved) x 8 cols (tx*4 / tx*4+32).
// y and RK accumulator in registers (cold spills OK); stage inputs ping-pong
// through two XOR-swizzled smem buffers (one barrier per stage).
__global__ void __launch_bounds__(NT, 2) ode_rk4_kernel(
    const float* __restrict__ x, const float* __restrict__ W,
    const float* __restrict__ bias, float* __restrict__ out)
{
    extern __shared__ float smem[];
    float* sW  = smem;                 // [64][64] k-major: sW[k*64+c] = W[c][k+1]
    float* swt = sW + DIM * DIM;       // [64] t-coefficients W[c][0]
    float* sb  = swt + DIM;            // [64] bias
    float* sB0 = sb + DIM;             // [128][64] stage input (ping), swizzled
    float* sB1 = sB0 + TILE * DIM;     // [128][64] stage input (pong), swizzled

    const int tid = threadIdx.x;
    const int tx  = tid & 7;           // 8 col-groups
    const int ty  = tid >> 3;          // 32 row-groups; rows = ty + 32*j
    const int CA  = tx * 4;            // cols CA..CA+3
    const int CB  = CA + 32;           // cols CB..CB+3
    const int row0 = blockIdx.x * TILE;

    // swizzled chunk offsets (in floats) for this thread's two col-chunks
    const int chA = ((tx ^ ty) & 15) << 2;
    const int chB = (((tx + 8) ^ ty) & 15) << 2;

    int roff[4];                       // smem row bases (floats)
    #pragma unroll
    for (int j = 0; j < 4; j++) roff[j] = (ty + 32 * j) * DIM;

    // ---- load weights into smem (k-major; conflict-free LDS.128 on read) ----
    for (int i = tid; i < DIM * DIM; i += NT){
        int k = i >> 6, c = i & 63;
        sW[i] = W[c * (DIM + 1) + k + 1];
    }
    if (tid < DIM){ swt[tid] = W[tid * (DIM + 1)]; sb[tid] = bias[tid]; }

    // ---- load y0, publish first stage input into sB0 (swizzled) ----
    float yv[4][8], av[4][8];
    #pragma unroll
    for (int j = 0; j < 4; j++){
        const float4* gx = reinterpret_cast<const float4*>(
            x + (size_t)(row0 + ty + 32 * j) * DIM);
        float4 vA = gx[tx];
        float4 vB = gx[tx + 8];
        yv[j][0]=vA.x; yv[j][1]=vA.y; yv[j][2]=vA.z; yv[j][3]=vA.w;
        yv[j][4]=vB.x; yv[j][5]=vB.y; yv[j][6]=vB.z; yv[j][7]=vB.w;
        *reinterpret_cast<float4*>(sB0 + roff[j] + chA) = vA;
        *reinterpret_cast<float4*>(sB0 + roff[j] + chB) = vB;
    }

    const float h  = 1.0f / NSTEP;
    const float h2 = 0.5f * h;
    const float h6 = h * (1.0f / 6.0f);

    u64 pre[4][4];   // packed fp32 pairs: 4 rows x 4 col-pairs

// GEMM at time TT reading swizzled stage input from BUF:
// pre[j][p] = t*wt + b + sum_k BUF[r][k]*sW[k][c]
#define DO_GEMM(TT, BUF) { \
    __syncthreads(); \
    { \
        u64 t2  = dup2(TT); \
        u64 p0 = fma2(t2, *reinterpret_cast<const u64*>(swt + CA),     \
                          *reinterpret_cast<const u64*>(sb  + CA));    \
        u64 p1 = fma2(t2, *reinterpret_cast<const u64*>(swt + CA + 2), \
                          *reinterpret_cast<const u64*>(sb  + CA + 2));\
        u64 p2 = fma2(t2, *reinterpret_cast<const u64*>(swt + CB),     \
                          *reinterpret_cast<const u64*>(sb  + CB));    \
        u64 p3 = fma2(t2, *reinterpret_cast<const u64*>(swt + CB + 2), \
                          *reinterpret_cast<const u64*>(sb  + CB + 2));\
        _Pragma("unroll") \
        for (int j = 0; j < 4; j++){ \
            pre[j][0] = p0; pre[j][1] = p1; pre[j][2] = p2; pre[j][3] = p3; \
        } \
    } \
    _Pragma("unroll 4") \
    for (int k4 = 0; k4 < 16; k4++){ \
        float4 a4[4]; \
        const int swz = ((k4 ^ ty) & 15) << 2; \
        _Pragma("unroll") \
        for (int j = 0; j < 4; j++) \
            a4[j] = *reinterpret_cast<const float4*>((BUF) + roff[j] + swz); \
        _Pragma("unroll") \
        for (int kk = 0; kk < 4; kk++){ \
            const float* wrow = sW + (k4 * 4 + kk) * DIM; \
            ulonglong2 wA = *reinterpret_cast<const ulonglong2*>(wrow + CA); \
            ulonglong2 wB = *reinterpret_cast<const ulonglong2*>(wrow + CB); \
            _Pragma("unroll") \
            for (int j = 0; j < 4; j++){ \
                float  as = reinterpret_cast<const float*>(&a4[j])[kk]; \
                u64 a = dup2(as); \
                pre[j][0] = fma2(a, wA.x, pre[j][0]); \
                pre[j][1] = fma2(a, wA.y, pre[j][1]); \
                pre[j][2] = fma2(a, wB.x, pre[j][2]); \
                pre[j][3] = fma2(a, wB.y, pre[j][3]); \
            } \
        } \
    } \
}

// unpack + activate one row's 8 pre-activations
#define ACT8(j, K) \
    float2 q0 = unpk(pre[j][0]), q1 = unpk(pre[j][1]); \
    float2 q2 = unpk(pre[j][2]), q3 = unpk(pre[j][3]); \
    float K[8] = { act(q0.x), act(q0.y), act(q1.x), act(q1.y), \
                   act(q2.x), act(q2.y), act(q3.x), act(q3.y) };

// epilogue: k = act(pre); acc-update; publish next stage input y + COEF*k
#define STAGE_EPI(WACC, COEF, FIRST, OUTB) { \
    _Pragma("unroll") \
    for (int j = 0; j < 4; j++){ \
        ACT8(j, kk) \
        _Pragma("unroll") \
        for (int i = 0; i < 8; i++){ \
            if (FIRST) av[j][i] = kk[i]; \
            else       av[j][i] = fmaf((WACC), kk[i], av[j][i]); \
        } \
        float4 wA4, wB4; \
        wA4.x = fmaf((COEF), kk[0], yv[j][0]); \
        wA4.y = fmaf((COEF), kk[1], yv[j][1]); \
        wA4.z = fmaf((COEF), kk[2], yv[j][2]); \
        wA4.w = fmaf((COEF), kk[3], yv[j][3]); \
        wB4.x = fmaf((COEF), kk[4], yv[j][4]); \
        wB4.y = fmaf((COEF), kk[5], yv[j][5]); \
        wB4.z = fmaf((COEF), kk[6], yv[j][6]); \
        wB4.w = fmaf((COEF), kk[7], yv[j][7]); \
        *reinterpret_cast<float4*>((OUTB) + roff[j] + chA) = wA4; \
        *reinterpret_cast<float4*>((OUTB) + roff[j] + chB) = wB4; \
    } \
}

// final stage: k4, y += h/6*(k1+2k2+2k3+k4), publish y for next step
#define STAGE_FIN(OUTB) { \
    _Pragma("unroll") \
    for (int j = 0; j < 4; j++){ \
        ACT8(j, kk) \
        _Pragma("unroll") \
        for (int i = 0; i < 8; i++){ \
            av[j][i] += kk[i]; \
            yv[j][i] = fmaf(h6, av[j][i], yv[j][i]); \
        } \
        float4 wA4, wB4; \
        wA4.x = yv[j][0]; wA4.y = yv[j][1]; wA4.z = yv[j][2]; wA4.w = yv[j][3]; \
        wB4.x = yv[j][4]; wB4.y = yv[j][5]; wB4.z = yv[j][6]; wB4.w = yv[j][7]; \
        *reinterpret_cast<float4*>((OUTB) + roff[j] + chA) = wA4; \
        *reinterpret_cast<float4*>((OUTB) + roff[j] + chB) = wB4; \
    } \
}

    #pragma unroll 1
    for (int s = 0; s < NSTEP; s++){
        float t0 = s * h;
        DO_GEMM(t0,      sB0);  STAGE_EPI(1.0f, h2, true,  sB1);   // k1
        DO_GEMM(t0 + h2, sB1);  STAGE_EPI(2.0f, h2, false, sB0);   // k2
        DO_GEMM(t0 + h2, sB0);  STAGE_EPI(2.0f, h,  false, sB1);   // k3
        DO_GEMM(t0 + h,  sB1);  STAGE_FIN(sB0);                    // k4
    }

    // ---- write result ----
    #pragma unroll
    for (int j = 0; j < 4; j++){
        float4* g = reinterpret_cast<float4*>(
            out + (size_t)(row0 + ty + 32 * j) * DIM);
        float4 vA, vB;
        vA.x=yv[j][0]; vA.y=yv[j][1]; vA.z=yv[j][2]; vA.w=yv[j][3];
        vB.x=yv[j][4]; vB.y=yv[j][5]; vB.z=yv[j][6]; vB.w=yv[j][7];
        g[tx]     = vA;
        g[tx + 8] = vB;
    }
}

extern "C" void kernel_launch(void* const* d_in, const int* in_sizes, int n_in,
                              void* d_out, int out_size)
{
    const float* x    = (const float*)d_in[0];
    const float* W    = (const float*)d_in[1];
    const float* bias = (const float*)d_in[2];
    float* out = (float*)d_out;

    int rows   = in_sizes[0] / DIM;     // 262144
    int blocks = rows / TILE;           // 2048

    size_t smem = (size_t)(DIM * DIM + 2 * DIM + 2 * TILE * DIM) * sizeof(float); // 82432 B
    cudaFuncSetAttribute(ode_rk4_kernel,
                         cudaFuncAttributeMaxDynamicSharedMemorySize, (int)smem);
    ode_rk4_kernel<<<blocks, NT, smem>>>(x, W, bias, out);
}

// round 9
// speedup vs baseline: 1.0458x; 1.0458x over previous
#include <cuda_runtime.h>

#define DIM   64
#define TILE  128
#define NT    128
#define NSTEP 2

typedef unsigned long long u64;

// ---- packed f32x2 helpers (Blackwell FFMA2: 2x FFMA throughput) ----
__device__ __forceinline__ u64 fma2(u64 a, u64 b, u64 c){
    u64 d; asm("fma.rn.f32x2 %0, %1, %2, %3;" : "=l"(d) : "l"(a), "l"(b), "l"(c)); return d;
}
__device__ __forceinline__ u64 pack2(float lo, float hi){
    u64 r; asm("mov.b64 %0, {%1, %2};" : "=l"(r) : "f"(lo), "f"(hi)); return r;
}
__device__ __forceinline__ u64 dup2(float a){ return pack2(a, a); }
__device__ __forceinline__ float2 unpk(u64 v){
    float2 f; asm("mov.b64 {%0, %1}, %2;" : "=f"(f.x), "=f"(f.y) : "l"(v)); return f;
}

// smooth_leaky_relu: 0.1*x + 0.9*softplus(x), numerically stable
// (MUFU work overlaps other warps' fma-pipe GEMM once warps are barrier-free)
__device__ __forceinline__ float act(float x){
    float sp = fmaxf(x, 0.f) + __logf(1.f + __expf(-fabsf(x)));
    return fmaf(0.9f, sp, 0.1f * x);
}

// One CTA integrates a TILE x 64 slab through all NSTEP RK4 steps.
// Each thread owns 8 rows (stride-16 interleaved) x 8 cols (split tx*4 / tx*4+32).
// KEY: stage rows {r : r mod 16 == ty} are written AND read only by the 8
// threads sharing ty — all within one warp. So stages need only __syncwarp(),
// and each warp free-runs through the whole integration: one warp's MUFU
// epilogue overlaps other warps' FFMA2 GEMM on disjoint pipes.
__global__ void __launch_bounds__(NT, 2) ode_rk4_kernel(
    const float* __restrict__ x, const float* __restrict__ W,
    const float* __restrict__ bias, float* __restrict__ out)
{
    extern __shared__ float smem[];
    float* sW  = smem;                 // [64][64] k-major: sW[k*64+c] = W[c][k+1]
    float* swt = sW + DIM * DIM;       // [64] t-coefficients W[c][0]
    float* sb  = swt + DIM;            // [64] bias
    float* sB0 = sb + DIM;             // [128][64] stage input (ping), swizzled
    float* sB1 = sB0 + TILE * DIM;     // [128][64] stage input (pong), swizzled

    const int tid = threadIdx.x;
    const int tx  = tid & 7;           // 8 col-groups
    const int ty  = tid >> 3;          // 16 row-groups; rows = ty + 16*j
    const int CA  = tx * 4;            // cols CA..CA+3
    const int CB  = CA + 32;           // cols CB..CB+3
    const int row0 = blockIdx.x * TILE;

    // swizzled chunk offsets (in floats) for this thread's two col-chunks
    const int chA = ((tx ^ ty) & 15) << 2;
    const int chB = (((tx + 8) ^ ty) & 15) << 2;

    int roff[8];                       // smem row bases (floats)
    #pragma unroll
    for (int j = 0; j < 8; j++) roff[j] = (ty + 16 * j) * DIM;

    // ---- load weights into smem (k-major; conflict-free LDS.128 on read) ----
    for (int i = tid; i < DIM * DIM; i += NT){
        int k = i >> 6, c = i & 63;
        sW[i] = W[c * (DIM + 1) + k + 1];
    }
    if (tid < DIM){ swt[tid] = W[tid * (DIM + 1)]; sb[tid] = bias[tid]; }
    __syncthreads();   // the ONLY block barrier: weights visible to all warps

    // ---- load y0, publish first stage input into sB0 (swizzled) ----
    float yv[8][8], av[8][8];
    #pragma unroll
    for (int j = 0; j < 8; j++){
        const float4* gx = reinterpret_cast<const float4*>(
            x + (size_t)(row0 + ty + 16 * j) * DIM);
        float4 vA = gx[tx];
        float4 vB = gx[tx + 8];
        yv[j][0]=vA.x; yv[j][1]=vA.y; yv[j][2]=vA.z; yv[j][3]=vA.w;
        yv[j][4]=vB.x; yv[j][5]=vB.y; yv[j][6]=vB.z; yv[j][7]=vB.w;
        *reinterpret_cast<float4*>(sB0 + roff[j] + chA) = vA;
        *reinterpret_cast<float4*>(sB0 + roff[j] + chB) = vB;
    }

    const float h  = 1.0f / NSTEP;
    const float h2 = 0.5f * h;
    const float h6 = h * (1.0f / 6.0f);

    u64 pre[8][4];   // packed fp32 pairs: 8 rows x 4 col-pairs

// GEMM at time TT reading swizzled stage input from BUF:
// pre[j][p] = t*wt + b + sum_k BUF[r][k]*sW[k][c]
// __syncwarp suffices: this warp's stage rows are warp-private.
#define DO_GEMM(TT, BUF) { \
    __syncwarp(); \
    { \
        u64 t2  = dup2(TT); \
        u64 p0 = fma2(t2, *reinterpret_cast<const u64*>(swt + CA),     \
                          *reinterpret_cast<const u64*>(sb  + CA));    \
        u64 p1 = fma2(t2, *reinterpret_cast<const u64*>(swt + CA + 2), \
                          *reinterpret_cast<const u64*>(sb  + CA + 2));\
        u64 p2 = fma2(t2, *reinterpret_cast<const u64*>(swt + CB),     \
                          *reinterpret_cast<const u64*>(sb  + CB));    \
        u64 p3 = fma2(t2, *reinterpret_cast<const u64*>(swt + CB + 2), \
                          *reinterpret_cast<const u64*>(sb  + CB + 2));\
        _Pragma("unroll") \
        for (int j = 0; j < 8; j++){ \
            pre[j][0] = p0; pre[j][1] = p1; pre[j][2] = p2; pre[j][3] = p3; \
        } \
    } \
    _Pragma("unroll 4") \
    for (int k4 = 0; k4 < 16; k4++){ \
        float4 a4[8]; \
        const int swz = ((k4 ^ ty) & 15) << 2; \
        _Pragma("unroll") \
        for (int j = 0; j < 8; j++) \
            a4[j] = *reinterpret_cast<const float4*>((BUF) + roff[j] + swz); \
        _Pragma("unroll") \
        for (int kk = 0; kk < 4; kk++){ \
            const float* wrow = sW + (k4 * 4 + kk) * DIM; \
            ulonglong2 wA = *reinterpret_cast<const ulonglong2*>(wrow + CA); \
            ulonglong2 wB = *reinterpret_cast<const ulonglong2*>(wrow + CB); \
            _Pragma("unroll") \
            for (int j = 0; j < 8; j++){ \
                float  as = reinterpret_cast<const float*>(&a4[j])[kk]; \
                u64 a = dup2(as); \
                pre[j][0] = fma2(a, wA.x, pre[j][0]); \
                pre[j][1] = fma2(a, wA.y, pre[j][1]); \
                pre[j][2] = fma2(a, wB.x, pre[j][2]); \
                pre[j][3] = fma2(a, wB.y, pre[j][3]); \
            } \
        } \
    } \
    __syncwarp(); \
}

// unpack + activate one row's 8 pre-activations
#define ACT8(j, K) \
    float2 q0 = unpk(pre[j][0]), q1 = unpk(pre[j][1]); \
    float2 q2 = unpk(pre[j][2]), q3 = unpk(pre[j][3]); \
    float K[8] = { act(q0.x), act(q0.y), act(q1.x), act(q1.y), \
                   act(q2.x), act(q2.y), act(q3.x), act(q3.y) };

// epilogue: k = act(pre); acc-update; publish next stage input y + COEF*k
#define STAGE_EPI(WACC, COEF, FIRST, OUTB) { \
    _Pragma("unroll") \
    for (int j = 0; j < 8; j++){ \
        ACT8(j, kk) \
        _Pragma("unroll") \
        for (int i = 0; i < 8; i++){ \
            if (FIRST) av[j][i] = kk[i]; \
            else       av[j][i] = fmaf((WACC), kk[i], av[j][i]); \
        } \
        float4 wA4, wB4; \
        wA4.x = fmaf((COEF), kk[0], yv[j][0]); \
        wA4.y = fmaf((COEF), kk[1], yv[j][1]); \
        wA4.z = fmaf((COEF), kk[2], yv[j][2]); \
        wA4.w = fmaf((COEF), kk[3], yv[j][3]); \
        wB4.x = fmaf((COEF), kk[4], yv[j][4]); \
        wB4.y = fmaf((COEF), kk[5], yv[j][5]); \
        wB4.z = fmaf((COEF), kk[6], yv[j][6]); \
        wB4.w = fmaf((COEF), kk[7], yv[j][7]); \
        *reinterpret_cast<float4*>((OUTB) + roff[j] + chA) = wA4; \
        *reinterpret_cast<float4*>((OUTB) + roff[j] + chB) = wB4; \
    } \
}

// final stage: k4, y += h/6*(k1+2k2+2k3+k4), publish y for next step
#define STAGE_FIN(OUTB) { \
    _Pragma("unroll") \
    for (int j = 0; j < 8; j++){ \
        ACT8(j, kk) \
        _Pragma("unroll") \
        for (int i = 0; i < 8; i++){ \
            av[j][i] += kk[i]; \
            yv[j][i] = fmaf(h6, av[j][i], yv[j][i]); \
        } \
        float4 wA4, wB4; \
        wA4.x = yv[j][0]; wA4.y = yv[j][1]; wA4.z = yv[j][2]; wA4.w = yv[j][3]; \
        wB4.x = yv[j][4]; wB4.y = yv[j][5]; wB4.z = yv[j][6]; wB4.w = yv[j][7]; \
        *reinterpret_cast<float4*>((OUTB) + roff[j] + chA) = wA4; \
        *reinterpret_cast<float4*>((OUTB) + roff[j] + chB) = wB4; \
    } \
}

    #pragma unroll 1
    for (int s = 0; s < NSTEP; s++){
        float t0 = s * h;
        DO_GEMM(t0,      sB0);  STAGE_EPI(1.0f, h2, true,  sB1);   // k1
        DO_GEMM(t0 + h2, sB1);  STAGE_EPI(2.0f, h2, false, sB0);   // k2
        DO_GEMM(t0 + h2, sB0);  STAGE_EPI(2.0f, h,  false, sB1);   // k3
        DO_GEMM(t0 + h,  sB1);  STAGE_FIN(sB0);                    // k4
    }

    // ---- write result ----
    #pragma unroll
    for (int j = 0; j < 8; j++){
        float4* g = reinterpret_cast<float4*>(
            out + (size_t)(row0 + ty + 16 * j) * DIM);
        float4 vA, vB;
        vA.x=yv[j][0]; vA.y=yv[j][1]; vA.z=yv[j][2]; vA.w=yv[j][3];
        vB.x=yv[j][4]; vB.y=yv[j][5]; vB.z=yv[j][6]; vB.w=yv[j][7];
        g[tx]     = vA;
        g[tx + 8] = vB;
    }
}

extern "C" void kernel_launch(void* const* d_in, const int* in_sizes, int n_in,
                              void* d_out, int out_size)
{
    const float* x    = (const float*)d_in[0];
    const float* W    = (const float*)d_in[1];
    const float* bias = (const float*)d_in[2];
    float* out = (float*)d_out;

    int rows   = in_sizes[0] / DIM;     // 262144
    int blocks = rows / TILE;           // 2048

    size_t smem = (size_t)(DIM * DIM + 2 * DIM + 2 * TILE * DIM) * sizeof(float); // 82432 B
    cudaFuncSetAttribute(ode_rk4_kernel,
                         cudaFuncAttributeMaxDynamicSharedMemorySize, (int)smem);
    ode_rk4_kernel<<<blocks, NT, smem>>>(x, W, bias, out);
}